// round 1
// baseline (speedup 1.0000x reference)
#include <cuda_runtime.h>
#include <math.h>

#define Bc 4
#define Sc 1024
#define Dc 768
#define Nc 12
#define Hc 64
#define Rc 2048
#define SCALE 0.125f
#define INFV 1000000.0f
#define EPSV 1e-9f

// ---------------- scratch (static device globals; no allocation) ----------------
__device__ float g_qh[Bc*Nc*Sc*Hc];   // [B,N,S,H]  q_head * scale
__device__ float g_kh[Bc*Nc*Sc*Hc];   // [B,N,S,H]
__device__ float g_vh[Bc*Nc*Sc*Hc];   // [B,N,S,H]
__device__ float g_rh[Nc*Rc*Hc];      // [N,R,H]
__device__ float g_tt[Bc*Nc*Sc*2];    // [B,N,S,{diff,same}]
__device__ float g_av[Bc*Nc*Sc*Hc];   // attn_vec [B,N,S,H]
__device__ float g_x [Bc*Sc*Dc];      // residual input to LN

// ---------------- projection GEMM: out = (A @ W)*scale + bias, scattered to [B',N,Srows,H]
__global__ __launch_bounds__(256)
void gemm_proj(const float* __restrict__ A, const float* __restrict__ W,
               const float* __restrict__ bias, float scale,
               int Srows, float* __restrict__ out) {
    __shared__ float As[16][65];
    __shared__ float Ws[16][65];
    int tid = threadIdx.x;
    int tx = tid & 15, ty = tid >> 4;
    int m0 = blockIdx.y * 64, n0 = blockIdx.x * 64;
    float acc[4][4] = {};
    for (int k0 = 0; k0 < Dc; k0 += 16) {
        {
            int k = tid & 15, mr = tid >> 4;
            #pragma unroll
            for (int p = 0; p < 4; p++) {
                int m = mr + p*16;
                As[k][m] = A[(size_t)(m0+m)*Dc + k0 + k];
            }
            int n = tid & 63, kk = tid >> 6;
            #pragma unroll
            for (int p = 0; p < 4; p++)
                Ws[kk + p*4][n] = W[(size_t)(k0+kk+p*4)*Dc + n0 + n];
        }
        __syncthreads();
        #pragma unroll
        for (int k = 0; k < 16; k++) {
            float a[4], b[4];
            #pragma unroll
            for (int i = 0; i < 4; i++) a[i] = As[k][ty*4+i];
            #pragma unroll
            for (int j = 0; j < 4; j++) b[j] = Ws[k][tx*4+j];
            #pragma unroll
            for (int i = 0; i < 4; i++)
                #pragma unroll
                for (int j = 0; j < 4; j++) acc[i][j] += a[i]*b[j];
        }
        __syncthreads();
    }
    #pragma unroll
    for (int i = 0; i < 4; i++) {
        int row = m0 + ty*4 + i;
        int bb = row / Srows, ss = row % Srows;
        #pragma unroll
        for (int j = 0; j < 4; j++) {
            int col = n0 + tx*4 + j;
            float v = acc[i][j] * scale;
            if (bias) v += bias[col];
            int nn = col >> 6, hh = col & 63;
            out[(((size_t)bb*Nc + nn)*Srows + ss)*Hc + hh] = v;
        }
    }
}

// ---------------- token-type bias: per (b,n,i) two scalars ----------------
__global__ __launch_bounds__(256)
void tt_kernel(const float* __restrict__ rsb, const float* __restrict__ seg) {
    int warp = threadIdx.x >> 5, lane = threadIdx.x & 31;
    int row = blockIdx.x * 8 + warp;                // [0, B*N*S)
    int n = (row / Sc) % Nc;
    const float* q = &g_qh[(size_t)row * Hc];       // row == ((b*N+n)*S+i) by layout
    float d = 0.f, s = 0.f;
    #pragma unroll
    for (int p = 0; p < 2; p++) {
        int h = lane + p*32;
        float qv = q[h] + rsb[n*Hc + h] * SCALE;
        d += qv * seg[(0*Nc + n)*Hc + h];
        s += qv * seg[(1*Nc + n)*Hc + h];
    }
    #pragma unroll
    for (int off = 16; off; off >>= 1) {
        d += __shfl_xor_sync(~0u, d, off);
        s += __shfl_xor_sync(~0u, s, off);
    }
    if (lane == 0) { g_tt[(size_t)row*2 + 0] = d; g_tt[(size_t)row*2 + 1] = s; }
}

// ---------------- fused attention: content + banded pos + tt, online softmax, P@V
extern __shared__ float sm[];
__global__ __launch_bounds__(256, 2)
void attn_kernel(const float* __restrict__ rwb, const float* __restrict__ rrb,
                 const unsigned char* __restrict__ ttm,
                 const float* __restrict__ amask_g,
                 const float* __restrict__ clsm) {
    float* qw    = sm;                 // 64*65
    float* qr    = qw + 64*65;
    float* kv    = qr + 64*65;         // K tile, reused for V
    float* ps    = kv + 64*65;         // P tile
    float* rs    = ps + 64*65;         // 128*65 r band
    float* amask = rs + 128*65;        // 64
    float* ttd   = amask + 64;         // 128

    int i0 = blockIdx.x * 64;
    int n  = blockIdx.y, b = blockIdx.z;
    int tid = threadIdx.x;
    int tx = tid & 15, ty = tid >> 4;

    const float* qbase = &g_qh[(((size_t)b*Nc + n)*Sc + i0) * Hc];
    const float* kbase = &g_kh[(((size_t)b*Nc + n)*Sc) * Hc];
    const float* vbase = &g_vh[(((size_t)b*Nc + n)*Sc) * Hc];
    const float* rbase = &g_rh[(size_t)n * Rc * Hc];

    for (int idx = tid; idx < 64*64; idx += 256) {
        int r = idx >> 6, h = idx & 63;
        float v = qbase[r*Hc + h];
        qw[r*65 + h] = v + rwb[n*Hc + h] * SCALE;
        qr[r*65 + h] = v + rrb[n*Hc + h] * SCALE;
    }
    for (int idx = tid; idx < 128; idx += 256)
        ttd[idx] = g_tt[(((size_t)b*Nc + n)*Sc + i0)*2 + idx];

    float m_[4], l_[4], o[4][4];
    #pragma unroll
    for (int a = 0; a < 4; a++) {
        m_[a] = -3.0e38f; l_[a] = 0.f;
        #pragma unroll
        for (int c = 0; c < 4; c++) o[a][c] = 0.f;
    }

    int ibase = 60 + 4*(tx - ty);

    for (int j0 = 0; j0 < Sc; j0 += 64) {
        __syncthreads();
        for (int idx = tid; idx < 64*64; idx += 256) {
            int r = idx >> 6, h = idx & 63;
            kv[r*65 + h] = kbase[(size_t)(j0 + r)*Hc + h];
        }
        int t_base = Sc - i0 - 63 + j0;
        for (int idx = tid; idx < 127*64; idx += 256) {
            int r = idx >> 6, h = idx & 63;
            int t = t_base + r;
            rs[r*65 + h] = (t >= 0 && t < Rc) ? rbase[(size_t)t*Hc + h] : 0.f;
        }
        if (tid < 64) amask[tid] = amask_g[b*Sc + j0 + tid];
        __syncthreads();

        float sc[4][4] = {}, pp[4][4] = {};
        #pragma unroll 4
        for (int h = 0; h < 64; h++) {
            float qa[4], ra[4], kb[4], rv[7];
            #pragma unroll
            for (int a = 0; a < 4; a++) {
                qa[a] = qw[(ty*4 + a)*65 + h];
                ra[a] = qr[(ty*4 + a)*65 + h];
            }
            #pragma unroll
            for (int c = 0; c < 4; c++) kb[c] = kv[(tx*4 + c)*65 + h];
            #pragma unroll
            for (int d = 0; d < 7; d++) rv[d] = rs[(ibase + d)*65 + h];
            #pragma unroll
            for (int a = 0; a < 4; a++)
                #pragma unroll
                for (int c = 0; c < 4; c++) {
                    sc[a][c] += qa[a] * kb[c];
                    pp[a][c] += ra[a] * rv[c - a + 3];
                }
        }

        float p[4][4];
        #pragma unroll
        for (int a = 0; a < 4; a++) {
            int ii = i0 + ty*4 + a;
            float tt_d = ttd[(ty*4 + a)*2 + 0];
            float tt_s = ttd[(ty*4 + a)*2 + 1];
            float mrow = -3.0e38f;
            #pragma unroll
            for (int c = 0; c < 4; c++) {
                int jj = j0 + tx*4 + c;
                float cls = clsm[(size_t)ii*Sc + jj];
                float ttv = ttm[((size_t)b*Sc + ii)*Sc + jj] ? tt_s : tt_d;
                float scv = sc[a][c] + cls*(pp[a][c] + ttv)
                            - INFV*(1.f - amask[tx*4 + c]);
                p[a][c] = scv;
                mrow = fmaxf(mrow, scv);
            }
            #pragma unroll
            for (int off = 8; off; off >>= 1)
                mrow = fmaxf(mrow, __shfl_xor_sync(~0u, mrow, off, 16));
            float mn = fmaxf(m_[a], mrow);
            float corr = __expf(m_[a] - mn);
            float lsum = 0.f;
            #pragma unroll
            for (int c = 0; c < 4; c++) { p[a][c] = __expf(p[a][c] - mn); lsum += p[a][c]; }
            #pragma unroll
            for (int off = 8; off; off >>= 1)
                lsum += __shfl_xor_sync(~0u, lsum, off, 16);
            l_[a] = l_[a]*corr + lsum;
            m_[a] = mn;
            #pragma unroll
            for (int c = 0; c < 4; c++) o[a][c] *= corr;
        }

        #pragma unroll
        for (int a = 0; a < 4; a++)
            #pragma unroll
            for (int c = 0; c < 4; c++)
                ps[(ty*4 + a)*65 + tx*4 + c] = p[a][c];
        __syncthreads();
        for (int idx = tid; idx < 64*64; idx += 256) {
            int r = idx >> 6, h = idx & 63;
            kv[r*65 + h] = vbase[(size_t)(j0 + r)*Hc + h];
        }
        __syncthreads();

        #pragma unroll 4
        for (int jl = 0; jl < 64; jl++) {
            float pa[4], vb[4];
            #pragma unroll
            for (int a = 0; a < 4; a++) pa[a] = ps[(ty*4 + a)*65 + jl];
            #pragma unroll
            for (int c = 0; c < 4; c++) vb[c] = kv[jl*65 + tx*4 + c];
            #pragma unroll
            for (int a = 0; a < 4; a++)
                #pragma unroll
                for (int c = 0; c < 4; c++) o[a][c] += pa[a] * vb[c];
        }
    }

    float* outb = &g_av[(((size_t)b*Nc + n)*Sc + i0) * Hc];
    #pragma unroll
    for (int a = 0; a < 4; a++) {
        float inv = 1.f / l_[a];
        #pragma unroll
        for (int c = 0; c < 4; c++)
            outb[(ty*4 + a)*Hc + tx*4 + c] = o[a][c] * inv;
    }
}

// ---------------- output projection + residual: g_x = attn_vec @ Wo + bo + query
__global__ __launch_bounds__(256)
void gemm_out(const float* __restrict__ Wo, const float* __restrict__ bo,
              const float* __restrict__ query) {
    __shared__ float As[16][65];
    __shared__ float Ws[16][65];
    int tid = threadIdx.x;
    int tx = tid & 15, ty = tid >> 4;
    int m0 = blockIdx.y * 64, n0 = blockIdx.x * 64;
    float acc[4][4] = {};
    for (int k0 = 0; k0 < Dc; k0 += 16) {
        {
            int k = tid & 15, mr = tid >> 4;
            #pragma unroll
            for (int p = 0; p < 4; p++) {
                int m = mr + p*16;
                int row = m0 + m, col = k0 + k;
                As[k][m] = g_av[((((size_t)(row >> 10))*Nc + (col >> 6))*Sc
                                  + (row & 1023))*Hc + (col & 63)];
            }
            int n = tid & 63, kk = tid >> 6;
            #pragma unroll
            for (int p = 0; p < 4; p++)
                Ws[kk + p*4][n] = Wo[(size_t)(k0+kk+p*4)*Dc + n0 + n];
        }
        __syncthreads();
        #pragma unroll
        for (int k = 0; k < 16; k++) {
            float a[4], bb[4];
            #pragma unroll
            for (int i = 0; i < 4; i++) a[i] = As[k][ty*4+i];
            #pragma unroll
            for (int j = 0; j < 4; j++) bb[j] = Ws[k][tx*4+j];
            #pragma unroll
            for (int i = 0; i < 4; i++)
                #pragma unroll
                for (int j = 0; j < 4; j++) acc[i][j] += a[i]*bb[j];
        }
        __syncthreads();
    }
    #pragma unroll
    for (int i = 0; i < 4; i++) {
        int row = m0 + ty*4 + i;
        #pragma unroll
        for (int j = 0; j < 4; j++) {
            int col = n0 + tx*4 + j;
            g_x[(size_t)row*Dc + col] = acc[i][j] + bo[col]
                                        + query[(size_t)row*Dc + col];
        }
    }
}

// ---------------- LayerNorm ----------------
__global__ __launch_bounds__(256)
void ln_kernel(const float* __restrict__ lng, const float* __restrict__ lnb,
               float* __restrict__ out) {
    __shared__ float red[8];
    __shared__ float stat;
    int row = blockIdx.x;
    const float* x = &g_x[(size_t)row * Dc];
    int t = threadIdx.x;
    float v[3];
    float s = 0.f;
    #pragma unroll
    for (int p = 0; p < 3; p++) { v[p] = x[t + p*256]; s += v[p]; }
    #pragma unroll
    for (int off = 16; off; off >>= 1) s += __shfl_xor_sync(~0u, s, off);
    if ((t & 31) == 0) red[t >> 5] = s;
    __syncthreads();
    if (t < 32) {
        float r = (t < 8) ? red[t] : 0.f;
        #pragma unroll
        for (int off = 4; off; off >>= 1) r += __shfl_xor_sync(~0u, r, off);
        if (t == 0) stat = r * (1.f / Dc);
    }
    __syncthreads();
    float mu = stat;
    float s2 = 0.f;
    #pragma unroll
    for (int p = 0; p < 3; p++) { float d = v[p] - mu; s2 += d*d; }
    #pragma unroll
    for (int off = 16; off; off >>= 1) s2 += __shfl_xor_sync(~0u, s2, off);
    if ((t & 31) == 0) red[t >> 5] = s2;
    __syncthreads();
    if (t < 32) {
        float r = (t < 8) ? red[t] : 0.f;
        #pragma unroll
        for (int off = 4; off; off >>= 1) r += __shfl_xor_sync(~0u, r, off);
        if (t == 0) stat = rsqrtf(r * (1.f / Dc) + EPSV);
    }
    __syncthreads();
    float rstd = stat;
    #pragma unroll
    for (int p = 0; p < 3; p++) {
        int i = t + p*256;
        out[(size_t)row*Dc + i] = (v[p] - mu) * rstd * lng[i] + lnb[i];
    }
}

// ---------------- launch ----------------
extern "C" void kernel_launch(void* const* d_in, const int* in_sizes, int n_in,
                              void* d_out, int out_size) {
    const float* query = (const float*)d_in[0];
    const float* key   = (const float*)d_in[1];
    const float* value = (const float*)d_in[2];
    const float* pose  = (const float*)d_in[3];
    const unsigned char* ttm = (const unsigned char*)d_in[4];
    const float* amask = (const float*)d_in[5];
    const float* clsm  = (const float*)d_in[6];
    const float* Wq    = (const float*)d_in[7];
    const float* Wk    = (const float*)d_in[8];
    const float* bk    = (const float*)d_in[9];
    const float* Wv    = (const float*)d_in[10];
    const float* bv    = (const float*)d_in[11];
    const float* rwb   = (const float*)d_in[12];
    const float* rrb   = (const float*)d_in[13];
    const float* rker  = (const float*)d_in[14];
    const float* rsb   = (const float*)d_in[15];
    const float* seg   = (const float*)d_in[16];
    const float* Wo    = (const float*)d_in[17];
    const float* bo    = (const float*)d_in[18];
    const float* lng   = (const float*)d_in[19];
    const float* lnb   = (const float*)d_in[20];
    float* out = (float*)d_out;

    float *qh, *kh, *vh, *rh;
    cudaGetSymbolAddress((void**)&qh, g_qh);
    cudaGetSymbolAddress((void**)&kh, g_kh);
    cudaGetSymbolAddress((void**)&vh, g_vh);
    cudaGetSymbolAddress((void**)&rh, g_rh);

    dim3 blk(256);
    gemm_proj<<<dim3(12, 64), blk>>>(query, Wq, nullptr, SCALE, Sc, qh);
    gemm_proj<<<dim3(12, 64), blk>>>(key,   Wk, bk,      1.0f,  Sc, kh);
    gemm_proj<<<dim3(12, 64), blk>>>(value, Wv, bv,      1.0f,  Sc, vh);
    gemm_proj<<<dim3(12, 32), blk>>>(pose,  rker, nullptr, 1.0f, Rc, rh);

    tt_kernel<<<Bc*Nc*Sc/8, blk>>>(rsb, seg);

    size_t smem = (size_t)(64*65*4 + 128*65 + 64 + 128) * sizeof(float); // 100,608 B
    cudaFuncSetAttribute(attn_kernel, cudaFuncAttributeMaxDynamicSharedMemorySize,
                         (int)smem);
    attn_kernel<<<dim3(Sc/64, Nc, Bc), blk, smem>>>(rwb, rrb, ttm, amask, clsm);

    gemm_out<<<dim3(12, 64), blk>>>(Wo, bo, query);

    ln_kernel<<<Bc*Sc, blk>>>(lng, lnb, out);
}